// round 14
// baseline (speedup 1.0000x reference)
#include <cuda_runtime.h>

#define B_ 2
#define C_ 128
#define T_ 512
#define F_ 64
#define H_ 32
#define D_ 32

typedef unsigned long long u64;

__device__ __forceinline__ u64 dup2(float a) {
    u64 r; asm("mov.b64 %0, {%1, %1};" : "=l"(r) : "f"(a)); return r;
}
__device__ __forceinline__ u64 pack2(float a, float b) {
    u64 r; asm("mov.b64 %0, {%1, %2};" : "=l"(r) : "f"(a), "f"(b)); return r;
}
__device__ __forceinline__ void ffma2(u64& d, u64 a, u64 b) {
    asm("fma.rn.f32x2 %0, %1, %2, %0;" : "+l"(d) : "l"(a), "l"(b));
}
__device__ __forceinline__ float2 unpk(u64 v) {
    float2 f; asm("mov.b64 {%0, %1}, %2;" : "=f"(f.x), "=f"(f.y) : "l"(v)); return f;
}

// Scratch (allocation-free rule: __device__ globals)
__device__ float g_xm1[B_*H_*T_*F_];   // (b,h,t,f)
__device__ float g_xf1[B_*H_*T_*F_];
__device__ float g_corr[B_*H_*T_*D_];  // (b,h,t,d)
__device__ float g_w[B_*T_*D_];

// ---------------------------------------------------------------------------
// Kernel 1: xm1[b,h,t,f] = sum_c xm[b,c,t,f]*w1[c,h] + b1[h]  (and xf1/w2/b2)
// Block = one (b,t). Thread owns (f, 8 consecutive h) as 4 f32x2 pairs.
// Double-buffered smem chunks, FFMA2 inner loop (8 FFMA2 per c per matrix-pair).
// ---------------------------------------------------------------------------
__global__ __launch_bounds__(256) void proj_kernel(
    const float* __restrict__ xm, const float* __restrict__ xf,
    const float* __restrict__ w1, const float* __restrict__ b1,
    const float* __restrict__ w2, const float* __restrict__ b2)
{
    __shared__ __align__(16) float w1s[C_][H_];
    __shared__ __align__(16) float w2s[C_][H_];
    __shared__ __align__(16) float xs[2][2][16][F_];

    const int b = blockIdx.x >> 9;
    const int t = blockIdx.x & 511;
    const int tid = threadIdx.x;

    for (int i = tid; i < C_*H_; i += 256) {
        w1s[i >> 5][i & 31] = w1[i];
        w2s[i >> 5][i & 31] = w2[i];
    }

    const int f  = tid & 63;
    const int hb = (tid >> 6) * 8;
    const int ccl = tid >> 4;
    const int ff4 = (tid & 15) * 4;

    u64 am[4], af[4];
    #pragma unroll
    for (int j = 0; j < 4; j++) {
        float2 bm = *(const float2*)&b1[hb + 2*j];
        float2 bf = *(const float2*)&b2[hb + 2*j];
        am[j] = pack2(bm.x, bm.y);
        af[j] = pack2(bf.x, bf.y);
    }

    const float* xmp = xm + (size_t)b * C_ * T_ * F_ + (size_t)t * F_;
    const float* xfp = xf + (size_t)b * C_ * T_ * F_ + (size_t)t * F_;

    float4 rm = *(const float4*)(xmp + (size_t)ccl * T_ * F_ + ff4);
    float4 rf = *(const float4*)(xfp + (size_t)ccl * T_ * F_ + ff4);

    for (int c0 = 0; c0 < C_; c0 += 16) {
        const int buf = (c0 >> 4) & 1;
        *(float4*)&xs[buf][0][ccl][ff4] = rm;
        *(float4*)&xs[buf][1][ccl][ff4] = rf;
        __syncthreads();
        if (c0 < C_ - 16) {
            rm = *(const float4*)(xmp + (size_t)(c0 + 16 + ccl) * T_ * F_ + ff4);
            rf = *(const float4*)(xfp + (size_t)(c0 + 16 + ccl) * T_ * F_ + ff4);
        }
        #pragma unroll
        for (int cc = 0; cc < 16; cc++) {
            u64 vmd = dup2(xs[buf][0][cc][f]);
            u64 vfd = dup2(xs[buf][1][cc][f]);
            ulonglong2 wA = *(const ulonglong2*)&w1s[c0 + cc][hb];
            ulonglong2 wB = *(const ulonglong2*)&w1s[c0 + cc][hb + 4];
            ulonglong2 uA = *(const ulonglong2*)&w2s[c0 + cc][hb];
            ulonglong2 uB = *(const ulonglong2*)&w2s[c0 + cc][hb + 4];
            ffma2(am[0], vmd, wA.x); ffma2(am[1], vmd, wA.y);
            ffma2(am[2], vmd, wB.x); ffma2(am[3], vmd, wB.y);
            ffma2(af[0], vfd, uA.x); ffma2(af[1], vfd, uA.y);
            ffma2(af[2], vfd, uB.x); ffma2(af[3], vfd, uB.y);
        }
    }

    size_t ob = ((size_t)(b * H_ + hb) * T_ + t) * F_ + f;
    #pragma unroll
    for (int j = 0; j < 4; j++) {
        float2 pm = unpk(am[j]);
        float2 pf = unpk(af[j]);
        g_xm1[ob + (size_t)(2*j)   * T_ * F_] = pm.x;
        g_xm1[ob + (size_t)(2*j+1) * T_ * F_] = pm.y;
        g_xf1[ob + (size_t)(2*j)   * T_ * F_] = pf.x;
        g_xf1[ob + (size_t)(2*j+1) * T_ * F_] = pf.y;
    }
}

// ---------------------------------------------------------------------------
// Kernel 2: corr[b,h,t,d] = sum_f xm1[b,h,t,f] * xf1[b,h,t+d-31,f]
// Block = (b,h, t-tile of 128). Thread tile = 2 adjacent t x 8 d (shares the
// banded window: 11 LDS.128 per 64 FMA). Parity-split smem (even/odd t rows
// in separate arrays) keeps the LDS.128 column access conflict-free.
// ---------------------------------------------------------------------------
__global__ __launch_bounds__(256) void corr_kernel()
{
    __shared__ __align__(16) float mE[64][68];   // xm1 rows, even t
    __shared__ __align__(16) float mO[64][68];   // odd t
    __shared__ __align__(16) float vE[80][68];   // window rows, even
    __shared__ __align__(16) float vO[80][68];   // odd

    const int bid = blockIdx.x;
    const int tt = bid & 3;
    const int h  = (bid >> 2) & (H_ - 1);
    const int b  = bid >> 7;
    const int t0 = tt * 128;
    const int tid = threadIdx.x;

    const float* mp = g_xm1 + (size_t)(b * H_ + h) * T_ * F_;
    const float* fp = g_xf1 + (size_t)(b * H_ + h) * T_ * F_;

    for (int i = tid; i < 128 * 16; i += 256) {
        int r = i >> 4, f4 = (i & 15) * 4;
        float4 v = *(const float4*)(mp + (size_t)(t0 + r) * F_ + f4);
        if (r & 1) *(float4*)&mO[r >> 1][f4] = v;
        else       *(float4*)&mE[r >> 1][f4] = v;
    }
    for (int i = tid; i < 159 * 16; i += 256) {
        int r = i >> 4, f4 = (i & 15) * 4;
        int tg = t0 + r - 31;
        float4 v = make_float4(0.f, 0.f, 0.f, 0.f);
        if (tg >= 0) v = *(const float4*)(fp + (size_t)tg * F_ + f4);
        if (r & 1) *(float4*)&vO[r >> 1][f4] = v;
        else       *(float4*)&vE[r >> 1][f4] = v;
    }
    __syncthreads();

    const int tl2 = (tid & 63) * 2;     // even base t-row (local)
    const int db  = (tid >> 6) * 8;     // d base (even)

    // acc2[i][k]: (even-f partial, odd-f partial) for t=tl2+i, d=db+k
    u64 acc2[2][8];
    #pragma unroll
    for (int i = 0; i < 2; i++)
        #pragma unroll
        for (int k = 0; k < 8; k++) acc2[i][k] = 0ULL;

    #pragma unroll
    for (int f4 = 0; f4 < F_; f4 += 4) {
        ulonglong2 m0 = *(const ulonglong2*)&mE[tl2 >> 1][f4];
        ulonglong2 m1 = *(const ulonglong2*)&mO[tl2 >> 1][f4];
        ulonglong2 vv[9];
        #pragma unroll
        for (int r = 0; r < 9; r++) {
            int lr = tl2 + db + r;      // logical window row; parity = r parity
            if (r & 1) vv[r] = *(const ulonglong2*)&vO[lr >> 1][f4];
            else       vv[r] = *(const ulonglong2*)&vE[lr >> 1][f4];
        }
        #pragma unroll
        for (int k = 0; k < 8; k++) {
            ffma2(acc2[0][k], m0.x, vv[k].x);
            ffma2(acc2[0][k], m0.y, vv[k].y);
            ffma2(acc2[1][k], m1.x, vv[k+1].x);
            ffma2(acc2[1][k], m1.y, vv[k+1].y);
        }
    }

    float* cp = g_corr + ((size_t)(b * H_ + h) * T_ + t0 + tl2) * D_ + db;
    #pragma unroll
    for (int i = 0; i < 2; i++) {
        float r[8];
        #pragma unroll
        for (int k = 0; k < 8; k++) {
            float2 p = unpk(acc2[i][k]);
            r[k] = p.x + p.y;
        }
        *(float4*)&cp[(size_t)i * D_]     = make_float4(r[0], r[1], r[2], r[3]);
        *(float4*)&cp[(size_t)i * D_ + 4] = make_float4(r[4], r[5], r[6], r[7]);
    }
}

// ---------------------------------------------------------------------------
// Kernel 3: conv(5x3 over h) + bias + causal mask + softmax(d)  (unchanged)
// ---------------------------------------------------------------------------
__global__ __launch_bounds__(256) void conv_softmax_kernel(
    const float* __restrict__ wc, const float* __restrict__ bc)
{
    __shared__ float wcs[H_ * 15];
    __shared__ float part[8][32];
    const int tid = threadIdx.x;
    for (int i = tid; i < H_ * 15; i += 256) wcs[i] = wc[i];
    __syncthreads();

    const int lane = tid & 31;
    const int wid  = tid >> 5;
    const int sub  = wid >> 2;
    const int hq   = (wid & 3) * 8;
    const int idx  = blockIdx.x * 2 + sub;
    const int b = idx >> 9;
    const int t = idx & 511;

    float acc = 0.f;
    #pragma unroll
    for (int hh = 0; hh < 8; hh++) {
        const int h = hq + hh;
        const float* cp = g_corr + (size_t)(b * H_ + h) * T_ * D_;
        const float* wr = &wcs[h * 15];
        #pragma unroll
        for (int kt = 0; kt < 5; kt++) {
            int ti = t + kt - 3;
            if (ti >= 0 && ti < T_) {
                float v  = cp[(size_t)ti * D_ + lane];
                float vm = __shfl_up_sync(0xffffffffu, v, 1);
                float vp = __shfl_down_sync(0xffffffffu, v, 1);
                if (lane == 0)  vm = 0.f;
                if (lane == 31) vp = 0.f;
                acc += wr[kt*3 + 0] * vm + wr[kt*3 + 1] * v + wr[kt*3 + 2] * vp;
            }
        }
    }
    part[wid][lane] = acc;
    __syncthreads();

    if ((wid & 3) == 0) {
        float a = part[wid][lane] + part[wid+1][lane]
                + part[wid+2][lane] + part[wid+3][lane] + bc[0];
        if (t + lane < D_ - 1) a = -10000000000000.0f;

        float m = a;
        #pragma unroll
        for (int o = 16; o > 0; o >>= 1) m = fmaxf(m, __shfl_xor_sync(0xffffffffu, m, o));
        float e = expf(a - m);
        float s = e;
        #pragma unroll
        for (int o = 16; o > 0; o >>= 1) s += __shfl_xor_sync(0xffffffffu, s, o);

        g_w[((size_t)b * T_ + t) * D_ + lane] = e / s;
    }
}

// ---------------------------------------------------------------------------
// Kernel 4: out[b,c,t,f] = sum_d w[b,t,d] * xf[b,c,t+d-31,f]
// Block = (b,c, t-tile 64). Warp owns 8 t-rows (warp-uniform => w reads are
// broadcasts); lane owns one f-pair (u64). Rotating 8-row register window,
// FFMA2 math. ~0.5B smem per FMA => fma/issue bound.
// ---------------------------------------------------------------------------
__global__ __launch_bounds__(256) void out_kernel(
    const float* __restrict__ xf, float* __restrict__ out)
{
    __shared__ __align__(16) float xfw[95][64];   // 23.75KB, stride 64 (256B)
    __shared__ __align__(16) float ws[64][32];    // 8KB

    const int bid = blockIdx.x;
    const int tt = bid & 7;
    const int c  = (bid >> 3) & (C_ - 1);
    const int b  = bid >> 10;
    const int t0 = tt * 64;
    const int tid = threadIdx.x;

    const float* xfp = xf + (size_t)(b * C_ + c) * T_ * F_;

    for (int i = tid; i < 95 * 16; i += 256) {
        int r = i >> 4, f4v = (i & 15) * 4;
        int tg = t0 + r - 31;
        float4 v = make_float4(0.f, 0.f, 0.f, 0.f);
        if (tg >= 0) v = *(const float4*)(xfp + (size_t)tg * F_ + f4v);
        *(float4*)&xfw[r][f4v] = v;
    }
    for (int i = tid; i < 64 * 32; i += 256) {
        int r = i >> 5, d = i & 31;
        ws[r][d] = g_w[((size_t)b * T_ + t0 + r) * D_ + d];
    }
    __syncthreads();

    const int lane = tid & 31;
    const int rowbase = (tid >> 5) * 8;    // warp-uniform 8 t-rows

    u64 acc[8];
    u64 win[8];
    #pragma unroll
    for (int r = 0; r < 8; r++) {
        acc[r] = 0ULL;
        win[r] = ((const u64*)xfw[rowbase + r])[lane];
    }

    #pragma unroll
    for (int d0 = 0; d0 < D_; d0 += 4) {
        float4 wv[8];
        #pragma unroll
        for (int r = 0; r < 8; r++)
            wv[r] = *(const float4*)&ws[rowbase + r][d0];   // broadcast

        #pragma unroll
        for (int s = 0; s < 4; s++) {
            const int d = d0 + s;
            #pragma unroll
            for (int r = 0; r < 8; r++) {
                float w = (s == 0) ? wv[r].x : (s == 1) ? wv[r].y
                        : (s == 2) ? wv[r].z : wv[r].w;
                ffma2(acc[r], dup2(w), win[(d + r) & 7]);
            }
            if (d < D_ - 1)
                win[d & 7] = ((const u64*)xfw[rowbase + d + 8])[lane];
        }
    }

    float* op = out + ((size_t)(b * C_ + c) * T_ + t0 + rowbase) * F_ + 2 * lane;
    #pragma unroll
    for (int r = 0; r < 8; r++)
        *(u64*)&op[(size_t)r * F_] = acc[r];
}

// ---------------------------------------------------------------------------
extern "C" void kernel_launch(void* const* d_in, const int* in_sizes, int n_in,
                              void* d_out, int out_size)
{
    const float* xm = (const float*)d_in[0];
    const float* xf = (const float*)d_in[1];
    const float* w1 = (const float*)d_in[2];
    const float* b1 = (const float*)d_in[3];
    const float* w2 = (const float*)d_in[4];
    const float* b2 = (const float*)d_in[5];
    const float* wc = (const float*)d_in[6];
    const float* bc = (const float*)d_in[7];
    float* out = (float*)d_out;

    proj_kernel<<<B_ * T_, 256>>>(xm, xf, w1, b1, w2, b2);
    corr_kernel<<<B_ * H_ * (T_ / 128), 256>>>();
    conv_softmax_kernel<<<B_ * T_ / 2, 256>>>(wc, bc);
    out_kernel<<<B_ * C_ * (T_ / 64), 256>>>(xf, out);
}